// round 9
// baseline (speedup 1.0000x reference)
#include <cuda_runtime.h>
#include <cuda_bf16.h>
#include <cstdint>
#include <math.h>

#define Bx 8
#define Ntok 512
#define Dm 768
#define Hh 12
#define HD 64
#define NL 6
#define DFF 3072
#define Mrows (Bx * Ntok)      // 4096
#define Tlen 8192
#define PATCH 16

// ---------------- scratch (device globals; no allocation) ----------------
__device__ float g_z[Mrows * Dm];
__device__ float g_h[Mrows * Dm];
__device__ float g_qkv[Mrows * 3 * Dm];
__device__ float g_enc[Bx * Dm];

__device__ __nv_bfloat16 g_hh[Mrows * Dm],  g_hl[Mrows * Dm];
__device__ __nv_bfloat16 g_oh[Mrows * Dm],  g_ol[Mrows * Dm];
__device__ __nv_bfloat16 g_fh[Mrows * DFF], g_fl[Mrows * DFF];

#define NQKV (NL * 3 * Dm * Dm)
#define NOUT (NL * Dm * Dm)
#define NFC1 (NL * DFF * Dm)
#define NFC2 (NL * Dm * DFF)
__device__ __nv_bfloat16 g_wqkv_h[NQKV], g_wqkv_l[NQKV];
__device__ __nv_bfloat16 g_wout_h[NOUT], g_wout_l[NOUT];
__device__ __nv_bfloat16 g_wfc1_h[NFC1], g_wfc1_l[NFC1];
__device__ __nv_bfloat16 g_wfc2_h[NFC2], g_wfc2_l[NFC2];

// ---------------- helpers ----------------
__device__ __forceinline__ void split_bf16(float x, __nv_bfloat16& h, __nv_bfloat16& l) {
    h = __float2bfloat16_rn(x);
    l = __float2bfloat16_rn(x - __bfloat162float(h));
}
__device__ __forceinline__ uint32_t sw64(uint32_t o) { return o ^ ((o >> 3) & 0x30); }
__device__ __forceinline__ uint32_t smem_u32(const void* p) {
    return (uint32_t)__cvta_generic_to_shared(p);
}
__device__ __forceinline__ void cp16(uint32_t dst, const void* src) {
    asm volatile("cp.async.cg.shared.global [%0], [%1], 16;" :: "r"(dst), "l"(src));
}
__device__ __forceinline__ void ldmx4(uint32_t* r, uint32_t addr) {
    asm volatile("ldmatrix.sync.aligned.m8n8.x4.shared.b16 {%0,%1,%2,%3}, [%4];"
                 : "=r"(r[0]), "=r"(r[1]), "=r"(r[2]), "=r"(r[3]) : "r"(addr));
}
__device__ __forceinline__ void mma16(float* c, const uint32_t* a, const uint32_t* b) {
    asm volatile("mma.sync.aligned.m16n8k16.row.col.f32.bf16.bf16.f32 "
                 "{%0,%1,%2,%3}, {%4,%5,%6,%7}, {%8,%9}, {%0,%1,%2,%3};"
                 : "+f"(c[0]), "+f"(c[1]), "+f"(c[2]), "+f"(c[3])
                 : "r"(a[0]), "r"(a[1]), "r"(a[2]), "r"(a[3]),
                   "r"(b[0]), "r"(b[1]));
}

// ---------------- weight split (vectorized x4) ----------------
__global__ void split_kernel(const float* __restrict__ src,
                             __nv_bfloat16* __restrict__ hi,
                             __nv_bfloat16* __restrict__ lo, int n) {
    int i = (blockIdx.x * 256 + threadIdx.x) * 4;
    if (i >= n) return;
    float4 v = *(const float4*)(src + i);
    __nv_bfloat16 h0, l0, h1, l1, h2, l2, h3, l3;
    split_bf16(v.x, h0, l0); split_bf16(v.y, h1, l1);
    split_bf16(v.z, h2, l2); split_bf16(v.w, h3, l3);
    ushort4 hv, lv;
    hv.x = *(uint16_t*)&h0; hv.y = *(uint16_t*)&h1; hv.z = *(uint16_t*)&h2; hv.w = *(uint16_t*)&h3;
    lv.x = *(uint16_t*)&l0; lv.y = *(uint16_t*)&l1; lv.z = *(uint16_t*)&l2; lv.w = *(uint16_t*)&l3;
    *(ushort4*)(hi + i) = hv;
    *(ushort4*)(lo + i) = lv;
}

// ---------------- patch embed + positional ----------------
__global__ void patch_embed_kernel(const float* __restrict__ x,
                                   const float* __restrict__ pp_w,
                                   const float* __restrict__ pp_b,
                                   const float* __restrict__ pe,
                                   float* __restrict__ z) {
    int idx = blockIdx.x * blockDim.x + threadIdx.x;
    if (idx >= Mrows * Dm) return;
    int row = idx / Dm;
    int d   = idx - row * Dm;
    int b = row >> 9;
    int n = row & 511;
    const float* xr = x + (size_t)b * Tlen + n * PATCH;
    const float* wr = pp_w + (size_t)d * PATCH;
    float s = pp_b[d];
#pragma unroll
    for (int p = 0; p < PATCH; ++p) s += xr[p] * wr[p];
    z[idx] = s + pe[(size_t)n * Dm + d];
}

// ---------------- LayerNorm: warp per row ----------------
template<int OUT>
__global__ __launch_bounds__(256)
void ln_kernel(const float* __restrict__ X,
               const float* __restrict__ gam,
               const float* __restrict__ bet,
               float* __restrict__ Yf,
               __nv_bfloat16* __restrict__ Yh,
               __nv_bfloat16* __restrict__ Yl) {
    const int warp = threadIdx.x >> 5, lane = threadIdx.x & 31;
    const int row = blockIdx.x * 8 + warp;
    const float4* xr = (const float4*)(X + (size_t)row * Dm);
    float4 v[6];
    float s = 0.f;
#pragma unroll
    for (int k = 0; k < 6; ++k) {
        v[k] = xr[lane + 32 * k];
        s += v[k].x + v[k].y + v[k].z + v[k].w;
    }
#pragma unroll
    for (int off = 16; off > 0; off >>= 1) s += __shfl_xor_sync(0xFFFFFFFFu, s, off);
    const float mean = s * (1.0f / Dm);
    float var = 0.f;
#pragma unroll
    for (int k = 0; k < 6; ++k) {
        float a = v[k].x - mean, b = v[k].y - mean, c = v[k].z - mean, d = v[k].w - mean;
        var += a * a + b * b + c * c + d * d;
    }
#pragma unroll
    for (int off = 16; off > 0; off >>= 1) var += __shfl_xor_sync(0xFFFFFFFFu, var, off);
    const float rstd = rsqrtf(var * (1.0f / Dm) + 1e-5f);

#pragma unroll
    for (int k = 0; k < 6; ++k) {
        int j4 = lane + 32 * k;
        float4 g = ((const float4*)gam)[j4];
        float4 b = ((const float4*)bet)[j4];
        float y0 = (v[k].x - mean) * rstd * g.x + b.x;
        float y1 = (v[k].y - mean) * rstd * g.y + b.y;
        float y2 = (v[k].z - mean) * rstd * g.z + b.z;
        float y3 = (v[k].w - mean) * rstd * g.w + b.w;
        if (OUT == 0) {
            ((float4*)(Yf + (size_t)row * Dm))[j4] = make_float4(y0, y1, y2, y3);
        } else {
            __nv_bfloat16 h0, l0, h1, l1, h2, l2, h3, l3;
            split_bf16(y0, h0, l0); split_bf16(y1, h1, l1);
            split_bf16(y2, h2, l2); split_bf16(y3, h3, l3);
            ushort4 hv, lv;
            hv.x = *(uint16_t*)&h0; hv.y = *(uint16_t*)&h1;
            hv.z = *(uint16_t*)&h2; hv.w = *(uint16_t*)&h3;
            lv.x = *(uint16_t*)&l0; lv.y = *(uint16_t*)&l1;
            lv.z = *(uint16_t*)&l2; lv.w = *(uint16_t*)&l3;
            ((ushort4*)(Yh + (size_t)row * Dm))[j4] = hv;
            ((ushort4*)(Yl + (size_t)row * Dm))[j4] = lv;
        }
    }
}

// ---------------- bf16x3 mma.sync GEMM, KTILE=32, 3 stages, 2 CTAs/SM ----------------
#define KTILE 32
#define ST_OP 8192                    // 128 x 32 bf16
#define STG (4 * ST_OP)               // 32768 per stage (Ah, Al, Wh, Wl)
#define NSTAGE 3
#define GEMM_SMEM (NSTAGE * STG + 1024)   // 99328

template<int EPI>
__global__ __launch_bounds__(256, 2)
void wgemm(const __nv_bfloat16* __restrict__ Ah, const __nv_bfloat16* __restrict__ Al,
           const __nv_bfloat16* __restrict__ Wh, const __nv_bfloat16* __restrict__ Wl,
           const float* __restrict__ Res, float* __restrict__ Cf,
           __nv_bfloat16* __restrict__ Chi, __nv_bfloat16* __restrict__ Clo,
           int Nn, int K) {
    extern __shared__ char dyn_smem[];
    const int tid = threadIdx.x, lane = tid & 31, wid = tid >> 5;
    const int warpM = wid & 1, warpN = wid >> 1;
    uint32_t raw = smem_u32(dyn_smem);
    uint32_t sb0 = (raw + 1023u) & ~1023u;

    const int mBase = blockIdx.y * 128, nBase = blockIdx.x * 128;
    const int KT = K >> 5;

    // loader: per operand tile = 512 x 16B chunks, 2 per thread
    uint32_t swl[2];
    const __nv_bfloat16 *pAh[2], *pAl[2], *pWh[2], *pWl[2];
#pragma unroll
    for (int i = 0; i < 2; ++i) {
        int q = tid + i * 256;
        int row = q >> 2, c = q & 3;
        swl[i] = sw64((uint32_t)(row * 64 + c * 16));
        size_t ga = (size_t)(mBase + row) * K + c * 8;
        size_t gw = (size_t)(nBase + row) * K + c * 8;
        pAh[i] = Ah + ga; pAl[i] = Al + ga;
        pWh[i] = Wh + gw; pWl[i] = Wl + gw;
    }

    float acc[4][4][4];
#pragma unroll
    for (int i = 0; i < 4; ++i)
#pragma unroll
        for (int j = 0; j < 4; ++j)
#pragma unroll
            for (int q = 0; q < 4; ++q) acc[i][j][q] = 0.f;

#define LOADSTG(kt)                                                              \
    do {                                                                         \
        const int kofs_ = (kt) * KTILE;                                          \
        const uint32_t sb_ = sb0 + ((kt) % NSTAGE) * STG;                        \
        _Pragma("unroll")                                                        \
        for (int i_ = 0; i_ < 2; ++i_) {                                         \
            cp16(sb_ + swl[i_],              pAh[i_] + kofs_);                   \
            cp16(sb_ + ST_OP + swl[i_],      pAl[i_] + kofs_);                   \
            cp16(sb_ + 2 * ST_OP + swl[i_],  pWh[i_] + kofs_);                   \
            cp16(sb_ + 3 * ST_OP + swl[i_],  pWl[i_] + kofs_);                   \
        }                                                                        \
        asm volatile("cp.async.commit_group;" ::: "memory");                     \
    } while (0)

    LOADSTG(0);
    LOADSTG(1);

    const int arow = warpM * 64 + (lane & 15);
    const int akb  = (lane >> 4) << 4;
    const int bprow = warpN * 32 + ((lane >> 4) & 1) * 8 + (lane & 7);
    const int bpkb  = ((lane >> 3) & 1) << 4;

    for (int kt = 0; kt < KT; ++kt) {
        if (kt + 1 < KT) {
            asm volatile("cp.async.wait_group 1;" ::: "memory");
        } else {
            asm volatile("cp.async.wait_group 0;" ::: "memory");
        }
        __syncthreads();
        if (kt + 2 < KT) LOADSTG(kt + 2);

        const uint32_t A0 = sb0 + (kt % NSTAGE) * STG;
        const uint32_t W0 = A0 + 2 * ST_OP;

#pragma unroll
        for (int kc = 0; kc < 2; ++kc) {
            uint32_t ah[4][4], al[4][4];
#pragma unroll
            for (int i = 0; i < 4; ++i) {
                uint32_t off = sw64((uint32_t)((arow + i * 16) * 64 + kc * 32 + akb));
                ldmx4(ah[i], A0 + off);
                ldmx4(al[i], A0 + ST_OP + off);
            }
            uint32_t bh[4][2], bl[4][2];
#pragma unroll
            for (int jp = 0; jp < 2; ++jp) {
                uint32_t off = sw64((uint32_t)((bprow + jp * 16) * 64 + kc * 32 + bpkb));
                uint32_t r[4];
                ldmx4(r, W0 + off);
                bh[2 * jp][0] = r[0]; bh[2 * jp][1] = r[1];
                bh[2 * jp + 1][0] = r[2]; bh[2 * jp + 1][1] = r[3];
                ldmx4(r, W0 + ST_OP + off);
                bl[2 * jp][0] = r[0]; bl[2 * jp][1] = r[1];
                bl[2 * jp + 1][0] = r[2]; bl[2 * jp + 1][1] = r[3];
            }
#pragma unroll
            for (int i = 0; i < 4; ++i)
#pragma unroll
                for (int j = 0; j < 4; ++j) {
                    mma16(acc[i][j], ah[i], bh[j]);
                    mma16(acc[i][j], ah[i], bl[j]);
                    mma16(acc[i][j], al[i], bh[j]);
                }
        }
    }

    const int erow = warpM * 64 + (lane >> 2);
    const int ecol = warpN * 32 + (lane & 3) * 2;
#pragma unroll
    for (int i = 0; i < 4; ++i) {
        int row0 = mBase + erow + i * 16;
#pragma unroll
        for (int j = 0; j < 4; ++j) {
            int col = nBase + ecol + j * 8;
            size_t g0 = (size_t)row0 * Nn + col;
            size_t g1 = g0 + (size_t)8 * Nn;
            float v0 = acc[i][j][0], v1 = acc[i][j][1];
            float v2 = acc[i][j][2], v3 = acc[i][j][3];
            if (EPI == 0) {
                *(float2*)(Cf + g0) = make_float2(v0, v1);
                *(float2*)(Cf + g1) = make_float2(v2, v3);
            } else if (EPI == 1) {
                float2 r0 = *(const float2*)(Res + g0);
                float2 r1 = *(const float2*)(Res + g1);
                *(float2*)(Cf + g0) = make_float2(v0 + r0.x, v1 + r0.y);
                *(float2*)(Cf + g1) = make_float2(v2 + r1.x, v3 + r1.y);
            } else {
                v0 = 0.5f * v0 * (1.0f + erff(v0 * 0.70710678118654752f));
                v1 = 0.5f * v1 * (1.0f + erff(v1 * 0.70710678118654752f));
                v2 = 0.5f * v2 * (1.0f + erff(v2 * 0.70710678118654752f));
                v3 = 0.5f * v3 * (1.0f + erff(v3 * 0.70710678118654752f));
                __nv_bfloat16 h0, l0, h1, l1, h2, l2, h3, l3;
                split_bf16(v0, h0, l0); split_bf16(v1, h1, l1);
                split_bf16(v2, h2, l2); split_bf16(v3, h3, l3);
                *(__nv_bfloat162*)(Chi + g0) = __nv_bfloat162(h0, h1);
                *(__nv_bfloat162*)(Clo + g0) = __nv_bfloat162(l0, l1);
                *(__nv_bfloat162*)(Chi + g1) = __nv_bfloat162(h2, h3);
                *(__nv_bfloat162*)(Clo + g1) = __nv_bfloat162(l2, l3);
            }
        }
    }
}

// ---------------- causal attention v3: 64 queries/CTA, 8 per warp ----------------
// dynamic smem (floats): Ks[64*65] | Vs[64*68] | Qs[64*65] | Ps[64*65]
#define ATT_KS   0
#define ATT_VS   (64 * 65)
#define ATT_QS   (ATT_VS + 64 * 68)
#define ATT_PS   (ATT_QS + 64 * 65)
#define ATT_SMEM ((ATT_PS + 64 * 65) * (int)sizeof(float))   // 67328 B

__global__ __launch_bounds__(256)
void attn_kernel(const float* __restrict__ qkv,
                 __nv_bfloat16* __restrict__ ohi, __nv_bfloat16* __restrict__ olo) {
    extern __shared__ float asm_[];
    float* Ks = asm_ + ATT_KS;   // [64][65]
    float* Vs = asm_ + ATT_VS;   // [64][68]
    float* Qs = asm_ + ATT_QS;   // [64][65]
    float* Ps = asm_ + ATT_PS;   // [64][65]
    const int b = blockIdx.z, h = blockIdx.y, qb = blockIdx.x;
    const int warp = threadIdx.x >> 5, lane = threadIdx.x & 31;
    const int tid = threadIdx.x;
    const int qBase = qb * 64;
    const int ql0 = warp * 8;

    // load Q: 64 rows x 16 float4 = 1024 float4; 4 per thread
    for (int i = tid; i < 1024; i += 256) {
        int q = i >> 4, dc = (i & 15) * 4;
        float4 v = *(const float4*)&qkv[((size_t)(b * Ntok + qBase + q)) * (3 * Dm) + h * HD + dc];
        Qs[q * 65 + dc + 0] = v.x; Qs[q * 65 + dc + 1] = v.y;
        Qs[q * 65 + dc + 2] = v.z; Qs[q * 65 + dc + 3] = v.w;
    }

    float accX[8], accY[8], Mx[8], Sum[8];
#pragma unroll
    for (int j = 0; j < 8; ++j) {
        accX[j] = 0.f; accY[j] = 0.f; Mx[j] = -INFINITY; Sum[j] = 0.f;
    }

    const int lastChunk = qb;   // (qBase + 63) >> 6

    for (int c = 0; c <= lastChunk; ++c) {
        __syncthreads();
        for (int i = tid; i < 1024; i += 256) {
            int m = i >> 4, dc = (i & 15) * 4;
            size_t base = ((size_t)(b * Ntok + c * 64 + m)) * (3 * Dm) + h * HD + dc;
            float4 kv = *(const float4*)&qkv[base + Dm];
            float4 vv = *(const float4*)&qkv[base + 2 * Dm];
            Ks[m * 65 + dc + 0] = kv.x; Ks[m * 65 + dc + 1] = kv.y;
            Ks[m * 65 + dc + 2] = kv.z; Ks[m * 65 + dc + 3] = kv.w;
            Vs[m * 68 + dc + 0] = vv.x; Vs[m * 68 + dc + 1] = vv.y;
            Vs[m * 68 + dc + 2] = vv.z; Vs[m * 68 + dc + 3] = vv.w;
        }
        __syncthreads();

        {
            float s1[8], s2[8];
#pragma unroll
            for (int j = 0; j < 8; ++j) { s1[j] = 0.f; s2[j] = 0.f; }
#pragma unroll
            for (int d = 0; d < 64; ++d) {
                float kd1 = Ks[lane * 65 + d];
                float kd2 = Ks[(lane + 32) * 65 + d];
#pragma unroll
                for (int j = 0; j < 8; ++j) {
                    float qd = Qs[(ql0 + j) * 65 + d];
                    s1[j] = fmaf(qd, kd1, s1[j]);
                    s2[j] = fmaf(qd, kd2, s2[j]);
                }
            }
            const int k1 = c * 64 + lane, k2 = k1 + 32;
#pragma unroll
            for (int j = 0; j < 8; ++j) {
                const int l = qBase + ql0 + j;
                if (l < c * 64) continue;    // fully masked chunk for this query
                float a1 = s1[j] * 0.125f, a2 = s2[j] * 0.125f;
                if (k1 > l) a1 = -INFINITY;
                if (k2 > l) a2 = -INFINITY;
                float cm = fmaxf(a1, a2);
#pragma unroll
                for (int off = 16; off > 0; off >>= 1)
                    cm = fmaxf(cm, __shfl_xor_sync(0xFFFFFFFFu, cm, off));
                float newM = fmaxf(Mx[j], cm);
                float scaleOld = __expf(Mx[j] - newM);
                float p1 = (k1 > l) ? 0.f : __expf(a1 - newM);
                float p2 = (k2 > l) ? 0.f : __expf(a2 - newM);
                float rs = p1 + p2;
#pragma unroll
                for (int off = 16; off > 0; off >>= 1)
                    rs += __shfl_xor_sync(0xFFFFFFFFu, rs, off);
                Sum[j] = Sum[j] * scaleOld + rs;
                Mx[j] = newM;
                accX[j] *= scaleOld; accY[j] *= scaleOld;
                Ps[(ql0 + j) * 65 + lane] = p1;
                Ps[(ql0 + j) * 65 + lane + 32] = p2;
            }
            __syncwarp();
#pragma unroll 4
            for (int m = 0; m < 64; ++m) {
                float2 v = *(const float2*)&Vs[m * 68 + 2 * lane];
#pragma unroll
                for (int j = 0; j < 8; ++j) {
                    float p = Ps[(ql0 + j) * 65 + m];
                    accX[j] = fmaf(p, v.x, accX[j]);
                    accY[j] = fmaf(p, v.y, accY[j]);
                }
            }
            __syncwarp();
        }
    }

#pragma unroll
    for (int j = 0; j < 8; ++j) {
        const int l = qBase + ql0 + j;
        float inv = 1.0f / Sum[j];
        size_t ob = ((size_t)(b * Ntok + l)) * Dm + h * HD + 2 * lane;
        __nv_bfloat16 hx, lx, hy, ly;
        split_bf16(accX[j] * inv, hx, lx);
        split_bf16(accY[j] * inv, hy, ly);
        *(__nv_bfloat162*)(ohi + ob) = __nv_bfloat162(hx, hy);
        *(__nv_bfloat162*)(olo + ob) = __nv_bfloat162(lx, ly);
    }
}

// ---------------- final mean over tokens ----------------
__global__ void mean_kernel(const float* __restrict__ hln, float* __restrict__ enc) {
    int idx = blockIdx.x * blockDim.x + threadIdx.x;
    if (idx >= Bx * Dm) return;
    int b = idx / Dm, d = idx - b * Dm;
    float s = 0.f;
    const float* base = hln + (size_t)b * Ntok * Dm + d;
    for (int n = 0; n < Ntok; ++n) s += base[(size_t)n * Dm];
    enc[idx] = s * (1.0f / Ntok);
}

// ---------------- head ----------------
__global__ void head_kernel(const float* __restrict__ enc,
                            const float* __restrict__ h1w, const float* __restrict__ h1b,
                            const float* __restrict__ h2w, const float* __restrict__ h2b,
                            float* __restrict__ out) {
    __shared__ float es[Dm];
    __shared__ float ys[Dm / 2];
    int b = blockIdx.x, tid = threadIdx.x;
    for (int j = tid; j < Dm; j += blockDim.x) es[j] = enc[(size_t)b * Dm + j];
    __syncthreads();
    int j = tid;
    float s = h1b[j];
    const float* wr = h1w + (size_t)j * Dm;
#pragma unroll 4
    for (int d = 0; d < Dm; ++d) s = fmaf(es[d], wr[d], s);
    ys[j] = fmaxf(s, 0.f);
    __syncthreads();
    if (tid < 2) {
        float s2 = h2b[tid];
        const float* w2 = h2w + (size_t)tid * (Dm / 2);
        for (int q = 0; q < Dm / 2; ++q) s2 = fmaf(ys[q], w2[q], s2);
        out[b * 2 + tid] = s2;
    }
}

// ---------------- launch ----------------
extern "C" void kernel_launch(void* const* d_in, const int* in_sizes, int n_in,
                              void* d_out, int out_size) {
    const float* x     = (const float*)d_in[0];
    const float* pp_w  = (const float*)d_in[1];
    const float* pp_b  = (const float*)d_in[2];
    const float* pe    = (const float*)d_in[3];
    const float* ln1_g = (const float*)d_in[4];
    const float* ln1_b = (const float*)d_in[5];
    const float* qkv_w = (const float*)d_in[6];
    const float* out_w = (const float*)d_in[7];
    const float* ln2_g = (const float*)d_in[8];
    const float* ln2_b = (const float*)d_in[9];
    const float* fc1_w = (const float*)d_in[10];
    const float* fc2_w = (const float*)d_in[11];
    const float* lnf_g = (const float*)d_in[12];
    const float* lnf_b = (const float*)d_in[13];
    const float* h1_w  = (const float*)d_in[14];
    const float* h1_b  = (const float*)d_in[15];
    const float* h2_w  = (const float*)d_in[16];
    const float* h2_b  = (const float*)d_in[17];

    float *z, *h, *qkv, *enc;
    __nv_bfloat16 *hh, *hl, *oh, *ol, *fh, *fl;
    __nv_bfloat16 *wqh, *wql, *woh, *wol, *w1h, *w1l, *w2h, *w2l;
    cudaGetSymbolAddress((void**)&z,   g_z);
    cudaGetSymbolAddress((void**)&h,   g_h);
    cudaGetSymbolAddress((void**)&qkv, g_qkv);
    cudaGetSymbolAddress((void**)&enc, g_enc);
    cudaGetSymbolAddress((void**)&hh,  g_hh);  cudaGetSymbolAddress((void**)&hl, g_hl);
    cudaGetSymbolAddress((void**)&oh,  g_oh);  cudaGetSymbolAddress((void**)&ol, g_ol);
    cudaGetSymbolAddress((void**)&fh,  g_fh);  cudaGetSymbolAddress((void**)&fl, g_fl);
    cudaGetSymbolAddress((void**)&wqh, g_wqkv_h); cudaGetSymbolAddress((void**)&wql, g_wqkv_l);
    cudaGetSymbolAddress((void**)&woh, g_wout_h); cudaGetSymbolAddress((void**)&wol, g_wout_l);
    cudaGetSymbolAddress((void**)&w1h, g_wfc1_h); cudaGetSymbolAddress((void**)&w1l, g_wfc1_l);
    cudaGetSymbolAddress((void**)&w2h, g_wfc2_h); cudaGetSymbolAddress((void**)&w2l, g_wfc2_l);

    cudaFuncSetAttribute(wgemm<0>, cudaFuncAttributeMaxDynamicSharedMemorySize, GEMM_SMEM);
    cudaFuncSetAttribute(wgemm<1>, cudaFuncAttributeMaxDynamicSharedMemorySize, GEMM_SMEM);
    cudaFuncSetAttribute(wgemm<2>, cudaFuncAttributeMaxDynamicSharedMemorySize, GEMM_SMEM);
    cudaFuncSetAttribute(attn_kernel, cudaFuncAttributeMaxDynamicSharedMemorySize, ATT_SMEM);

    split_kernel<<<NQKV / 1024, 256>>>(qkv_w, wqh, wql, NQKV);
    split_kernel<<<NOUT / 1024, 256>>>(out_w, woh, wol, NOUT);
    split_kernel<<<NFC1 / 1024, 256>>>(fc1_w, w1h, w1l, NFC1);
    split_kernel<<<NFC2 / 1024, 256>>>(fc2_w, w2h, w2l, NFC2);

    patch_embed_kernel<<<(Mrows * Dm + 255) / 256, 256>>>(x, pp_w, pp_b, pe, z);

    for (int i = 0; i < NL; ++i) {
        ln_kernel<1><<<Mrows / 8, 256>>>(z, ln1_g + i * Dm, ln1_b + i * Dm, nullptr, hh, hl);
        wgemm<0><<<dim3((3 * Dm) / 128, Mrows / 128), 256, GEMM_SMEM>>>(
            hh, hl, wqh + (size_t)i * 3 * Dm * Dm, wql + (size_t)i * 3 * Dm * Dm,
            nullptr, qkv, nullptr, nullptr, 3 * Dm, Dm);
        attn_kernel<<<dim3(Ntok / 64, Hh, Bx), 256, ATT_SMEM>>>(qkv, oh, ol);
        wgemm<1><<<dim3(Dm / 128, Mrows / 128), 256, GEMM_SMEM>>>(
            oh, ol, woh + (size_t)i * Dm * Dm, wol + (size_t)i * Dm * Dm,
            z, z, nullptr, nullptr, Dm, Dm);
        ln_kernel<1><<<Mrows / 8, 256>>>(z, ln2_g + i * Dm, ln2_b + i * Dm, nullptr, hh, hl);
        wgemm<2><<<dim3(DFF / 128, Mrows / 128), 256, GEMM_SMEM>>>(
            hh, hl, w1h + (size_t)i * DFF * Dm, w1l + (size_t)i * DFF * Dm,
            nullptr, nullptr, fh, fl, DFF, Dm);
        wgemm<1><<<dim3(Dm / 128, Mrows / 128), 256, GEMM_SMEM>>>(
            fh, fl, w2h + (size_t)i * Dm * DFF, w2l + (size_t)i * Dm * DFF,
            z, z, nullptr, nullptr, Dm, DFF);
    }

    ln_kernel<0><<<Mrows / 8, 256>>>(z, lnf_g, lnf_b, h, nullptr, nullptr);
    mean_kernel<<<(Bx * Dm + 255) / 256, 256>>>(h, enc);
    head_kernel<<<Bx, Dm / 2>>>(enc, h1_w, h1_b, h2_w, h2_b, (float*)d_out);
}

// round 10
// speedup vs baseline: 1.0651x; 1.0651x over previous
#include <cuda_runtime.h>
#include <cuda_bf16.h>
#include <cstdint>
#include <math.h>

#define Bx 8
#define Ntok 512
#define Dm 768
#define Hh 12
#define HD 64
#define NL 6
#define DFF 3072
#define Mrows (Bx * Ntok)      // 4096
#define Tlen 8192
#define PATCH 16

// ---------------- scratch (device globals; no allocation) ----------------
__device__ float g_z[Mrows * Dm];
__device__ float g_h[Mrows * Dm];
__device__ float g_qkv[Mrows * 3 * Dm];
__device__ float g_enc[Bx * Dm];

__device__ __nv_bfloat16 g_hh[Mrows * Dm],  g_hl[Mrows * Dm];
__device__ __nv_bfloat16 g_oh[Mrows * Dm],  g_ol[Mrows * Dm];
__device__ __nv_bfloat16 g_fh[Mrows * DFF], g_fl[Mrows * DFF];

#define NQKV (NL * 3 * Dm * Dm)
#define NOUT (NL * Dm * Dm)
#define NFC1 (NL * DFF * Dm)
#define NFC2 (NL * Dm * DFF)
__device__ __nv_bfloat16 g_wqkv_h[NQKV], g_wqkv_l[NQKV];
__device__ __nv_bfloat16 g_wout_h[NOUT], g_wout_l[NOUT];
__device__ __nv_bfloat16 g_wfc1_h[NFC1], g_wfc1_l[NFC1];
__device__ __nv_bfloat16 g_wfc2_h[NFC2], g_wfc2_l[NFC2];

// ---------------- helpers ----------------
__device__ __forceinline__ void split_bf16(float x, __nv_bfloat16& h, __nv_bfloat16& l) {
    h = __float2bfloat16_rn(x);
    l = __float2bfloat16_rn(x - __bfloat162float(h));
}
__device__ __forceinline__ uint32_t sw128(uint32_t o) { return o ^ ((o >> 3) & 0x70); }
__device__ __forceinline__ uint32_t smem_u32(const void* p) {
    return (uint32_t)__cvta_generic_to_shared(p);
}
__device__ __forceinline__ void cp16(uint32_t dst, const void* src) {
    asm volatile("cp.async.cg.shared.global [%0], [%1], 16;" :: "r"(dst), "l"(src));
}
__device__ __forceinline__ void ldmx4(uint32_t* r, uint32_t addr) {
    asm volatile("ldmatrix.sync.aligned.m8n8.x4.shared.b16 {%0,%1,%2,%3}, [%4];"
                 : "=r"(r[0]), "=r"(r[1]), "=r"(r[2]), "=r"(r[3]) : "r"(addr));
}
__device__ __forceinline__ void mma16(float* c, const uint32_t* a, const uint32_t* b) {
    asm volatile("mma.sync.aligned.m16n8k16.row.col.f32.bf16.bf16.f32 "
                 "{%0,%1,%2,%3}, {%4,%5,%6,%7}, {%8,%9}, {%0,%1,%2,%3};"
                 : "+f"(c[0]), "+f"(c[1]), "+f"(c[2]), "+f"(c[3])
                 : "r"(a[0]), "r"(a[1]), "r"(a[2]), "r"(a[3]),
                   "r"(b[0]), "r"(b[1]));
}

// ---------------- weight split (vectorized x4) ----------------
__global__ void split_kernel(const float* __restrict__ src,
                             __nv_bfloat16* __restrict__ hi,
                             __nv_bfloat16* __restrict__ lo, int n) {
    int i = (blockIdx.x * 256 + threadIdx.x) * 4;
    if (i >= n) return;
    float4 v = *(const float4*)(src + i);
    __nv_bfloat16 h0, l0, h1, l1, h2, l2, h3, l3;
    split_bf16(v.x, h0, l0); split_bf16(v.y, h1, l1);
    split_bf16(v.z, h2, l2); split_bf16(v.w, h3, l3);
    ushort4 hv, lv;
    hv.x = *(uint16_t*)&h0; hv.y = *(uint16_t*)&h1; hv.z = *(uint16_t*)&h2; hv.w = *(uint16_t*)&h3;
    lv.x = *(uint16_t*)&l0; lv.y = *(uint16_t*)&l1; lv.z = *(uint16_t*)&l2; lv.w = *(uint16_t*)&l3;
    *(ushort4*)(hi + i) = hv;
    *(ushort4*)(lo + i) = lv;
}

// ---------------- patch embed + positional ----------------
__global__ void patch_embed_kernel(const float* __restrict__ x,
                                   const float* __restrict__ pp_w,
                                   const float* __restrict__ pp_b,
                                   const float* __restrict__ pe,
                                   float* __restrict__ z) {
    int idx = blockIdx.x * blockDim.x + threadIdx.x;
    if (idx >= Mrows * Dm) return;
    int row = idx / Dm;
    int d   = idx - row * Dm;
    int b = row >> 9;
    int n = row & 511;
    const float* xr = x + (size_t)b * Tlen + n * PATCH;
    const float* wr = pp_w + (size_t)d * PATCH;
    float s = pp_b[d];
#pragma unroll
    for (int p = 0; p < PATCH; ++p) s += xr[p] * wr[p];
    z[idx] = s + pe[(size_t)n * Dm + d];
}

// ---------------- LayerNorm: warp per row ----------------
template<int OUT>
__global__ __launch_bounds__(256)
void ln_kernel(const float* __restrict__ X,
               const float* __restrict__ gam,
               const float* __restrict__ bet,
               float* __restrict__ Yf,
               __nv_bfloat16* __restrict__ Yh,
               __nv_bfloat16* __restrict__ Yl) {
    const int warp = threadIdx.x >> 5, lane = threadIdx.x & 31;
    const int row = blockIdx.x * 8 + warp;
    const float4* xr = (const float4*)(X + (size_t)row * Dm);
    float4 v[6];
    float s = 0.f;
#pragma unroll
    for (int k = 0; k < 6; ++k) {
        v[k] = xr[lane + 32 * k];
        s += v[k].x + v[k].y + v[k].z + v[k].w;
    }
#pragma unroll
    for (int off = 16; off > 0; off >>= 1) s += __shfl_xor_sync(0xFFFFFFFFu, s, off);
    const float mean = s * (1.0f / Dm);
    float var = 0.f;
#pragma unroll
    for (int k = 0; k < 6; ++k) {
        float a = v[k].x - mean, b = v[k].y - mean, c = v[k].z - mean, d = v[k].w - mean;
        var += a * a + b * b + c * c + d * d;
    }
#pragma unroll
    for (int off = 16; off > 0; off >>= 1) var += __shfl_xor_sync(0xFFFFFFFFu, var, off);
    const float rstd = rsqrtf(var * (1.0f / Dm) + 1e-5f);

#pragma unroll
    for (int k = 0; k < 6; ++k) {
        int j4 = lane + 32 * k;
        float4 g = ((const float4*)gam)[j4];
        float4 b = ((const float4*)bet)[j4];
        float y0 = (v[k].x - mean) * rstd * g.x + b.x;
        float y1 = (v[k].y - mean) * rstd * g.y + b.y;
        float y2 = (v[k].z - mean) * rstd * g.z + b.z;
        float y3 = (v[k].w - mean) * rstd * g.w + b.w;
        if (OUT == 0) {
            ((float4*)(Yf + (size_t)row * Dm))[j4] = make_float4(y0, y1, y2, y3);
        } else {
            __nv_bfloat16 h0, l0, h1, l1, h2, l2, h3, l3;
            split_bf16(y0, h0, l0); split_bf16(y1, h1, l1);
            split_bf16(y2, h2, l2); split_bf16(y3, h3, l3);
            ushort4 hv, lv;
            hv.x = *(uint16_t*)&h0; hv.y = *(uint16_t*)&h1;
            hv.z = *(uint16_t*)&h2; hv.w = *(uint16_t*)&h3;
            lv.x = *(uint16_t*)&l0; lv.y = *(uint16_t*)&l1;
            lv.z = *(uint16_t*)&l2; lv.w = *(uint16_t*)&l3;
            ((ushort4*)(Yh + (size_t)row * Dm))[j4] = hv;
            ((ushort4*)(Yl + (size_t)row * Dm))[j4] = lv;
        }
    }
}

// ---------------- bf16x3 mma.sync GEMM, KTILE=64, 3 stages (round-8 best) ----------------
#define KTILE 64
#define ST_OP 16384
#define STG (4 * ST_OP)
#define NSTAGE 3
#define GEMM_SMEM (NSTAGE * STG + 1024)

template<int EPI>
__global__ __launch_bounds__(256, 1)
void wgemm(const __nv_bfloat16* __restrict__ Ah, const __nv_bfloat16* __restrict__ Al,
           const __nv_bfloat16* __restrict__ Wh, const __nv_bfloat16* __restrict__ Wl,
           const float* __restrict__ Res, float* __restrict__ Cf,
           __nv_bfloat16* __restrict__ Chi, __nv_bfloat16* __restrict__ Clo,
           int Nn, int K) {
    extern __shared__ char dyn_smem[];
    const int tid = threadIdx.x, lane = tid & 31, wid = tid >> 5;
    const int warpM = wid & 1, warpN = wid >> 1;
    uint32_t raw = smem_u32(dyn_smem);
    uint32_t sb0 = (raw + 1023u) & ~1023u;

    const int mBase = blockIdx.y * 128, nBase = blockIdx.x * 128;
    const int KT = K >> 6;

    uint32_t swl[4];
    const __nv_bfloat16 *pAh[4], *pAl[4], *pWh[4], *pWl[4];
#pragma unroll
    for (int i = 0; i < 4; ++i) {
        int q = tid + i * 256;
        int row = q >> 3, c = q & 7;
        swl[i] = sw128((uint32_t)(row * 128 + c * 16));
        size_t ga = (size_t)(mBase + row) * K + c * 8;
        size_t gw = (size_t)(nBase + row) * K + c * 8;
        pAh[i] = Ah + ga; pAl[i] = Al + ga;
        pWh[i] = Wh + gw; pWl[i] = Wl + gw;
    }

    float acc[4][4][4];
#pragma unroll
    for (int i = 0; i < 4; ++i)
#pragma unroll
        for (int j = 0; j < 4; ++j)
#pragma unroll
            for (int q = 0; q < 4; ++q) acc[i][j][q] = 0.f;

#define LOADSTG(kt)                                                              \
    do {                                                                         \
        const int kofs_ = (kt) * KTILE;                                          \
        const uint32_t sb_ = sb0 + ((kt) % NSTAGE) * STG;                        \
        _Pragma("unroll")                                                        \
        for (int i_ = 0; i_ < 4; ++i_) {                                         \
            cp16(sb_ + swl[i_],              pAh[i_] + kofs_);                   \
            cp16(sb_ + ST_OP + swl[i_],      pAl[i_] + kofs_);                   \
            cp16(sb_ + 2 * ST_OP + swl[i_],  pWh[i_] + kofs_);                   \
            cp16(sb_ + 3 * ST_OP + swl[i_],  pWl[i_] + kofs_);                   \
        }                                                                        \
        asm volatile("cp.async.commit_group;" ::: "memory");                     \
    } while (0)

    LOADSTG(0);
    LOADSTG(1);

    const int arow = warpM * 64 + (lane & 15);
    const int akb  = (lane >> 4) << 4;
    const int bprow = warpN * 32 + ((lane >> 4) & 1) * 8 + (lane & 7);
    const int bpkb  = ((lane >> 3) & 1) << 4;

    for (int kt = 0; kt < KT; ++kt) {
        if (kt + 1 < KT) {
            asm volatile("cp.async.wait_group 1;" ::: "memory");
        } else {
            asm volatile("cp.async.wait_group 0;" ::: "memory");
        }
        __syncthreads();
        if (kt + 2 < KT) LOADSTG(kt + 2);

        const uint32_t A0 = sb0 + (kt % NSTAGE) * STG;
        const uint32_t W0 = A0 + 2 * ST_OP;

#pragma unroll
        for (int kc = 0; kc < 4; ++kc) {
            uint32_t ah[4][4], al[4][4];
#pragma unroll
            for (int i = 0; i < 4; ++i) {
                uint32_t off = sw128((uint32_t)((arow + i * 16) * 128 + kc * 32 + akb));
                ldmx4(ah[i], A0 + off);
                ldmx4(al[i], A0 + ST_OP + off);
            }
            uint32_t bh[4][2], bl[4][2];
#pragma unroll
            for (int jp = 0; jp < 2; ++jp) {
                uint32_t off = sw128((uint32_t)((bprow + jp * 16) * 128 + kc * 32 + bpkb));
                uint32_t r[4];
                ldmx4(r, W0 + off);
                bh[2 * jp][0] = r[0]; bh[2 * jp][1] = r[1];
                bh[2 * jp + 1][0] = r[2]; bh[2 * jp + 1][1] = r[3];
                ldmx4(r, W0 + ST_OP + off);
                bl[2 * jp][0] = r[0]; bl[2 * jp][1] = r[1];
                bl[2 * jp + 1][0] = r[2]; bl[2 * jp + 1][1] = r[3];
            }
#pragma unroll
            for (int i = 0; i < 4; ++i)
#pragma unroll
                for (int j = 0; j < 4; ++j) {
                    mma16(acc[i][j], ah[i], bh[j]);
                    mma16(acc[i][j], ah[i], bl[j]);
                    mma16(acc[i][j], al[i], bh[j]);
                }
        }
    }

    const int erow = warpM * 64 + (lane >> 2);
    const int ecol = warpN * 32 + (lane & 3) * 2;
#pragma unroll
    for (int i = 0; i < 4; ++i) {
        int row0 = mBase + erow + i * 16;
#pragma unroll
        for (int j = 0; j < 4; ++j) {
            int col = nBase + ecol + j * 8;
            size_t g0 = (size_t)row0 * Nn + col;
            size_t g1 = g0 + (size_t)8 * Nn;
            float v0 = acc[i][j][0], v1 = acc[i][j][1];
            float v2 = acc[i][j][2], v3 = acc[i][j][3];
            if (EPI == 0) {
                *(float2*)(Cf + g0) = make_float2(v0, v1);
                *(float2*)(Cf + g1) = make_float2(v2, v3);
            } else if (EPI == 1) {
                float2 r0 = *(const float2*)(Res + g0);
                float2 r1 = *(const float2*)(Res + g1);
                *(float2*)(Cf + g0) = make_float2(v0 + r0.x, v1 + r0.y);
                *(float2*)(Cf + g1) = make_float2(v2 + r1.x, v3 + r1.y);
            } else {
                v0 = 0.5f * v0 * (1.0f + erff(v0 * 0.70710678118654752f));
                v1 = 0.5f * v1 * (1.0f + erff(v1 * 0.70710678118654752f));
                v2 = 0.5f * v2 * (1.0f + erff(v2 * 0.70710678118654752f));
                v3 = 0.5f * v3 * (1.0f + erff(v3 * 0.70710678118654752f));
                __nv_bfloat16 h0, l0, h1, l1, h2, l2, h3, l3;
                split_bf16(v0, h0, l0); split_bf16(v1, h1, l1);
                split_bf16(v2, h2, l2); split_bf16(v3, h3, l3);
                *(__nv_bfloat162*)(Chi + g0) = __nv_bfloat162(h0, h1);
                *(__nv_bfloat162*)(Clo + g0) = __nv_bfloat162(l0, l1);
                *(__nv_bfloat162*)(Chi + g1) = __nv_bfloat162(h2, h3);
                *(__nv_bfloat162*)(Clo + g1) = __nv_bfloat162(l2, l3);
            }
        }
    }
}

// ---------------- causal attention v3: 64 queries/CTA, 8 per warp ----------------
#define ATT_KS   0
#define ATT_VS   (64 * 65)
#define ATT_QS   (ATT_VS + 64 * 68)
#define ATT_PS   (ATT_QS + 64 * 65)
#define ATT_SMEM ((ATT_PS + 64 * 65) * (int)sizeof(float))   // 67328 B

__global__ __launch_bounds__(256)
void attn_kernel(const float* __restrict__ qkv,
                 __nv_bfloat16* __restrict__ ohi, __nv_bfloat16* __restrict__ olo) {
    extern __shared__ float asm_[];
    float* Ks = asm_ + ATT_KS;
    float* Vs = asm_ + ATT_VS;
    float* Qs = asm_ + ATT_QS;
    float* Ps = asm_ + ATT_PS;
    const int b = blockIdx.z, h = blockIdx.y, qb = blockIdx.x;
    const int warp = threadIdx.x >> 5, lane = threadIdx.x & 31;
    const int tid = threadIdx.x;
    const int qBase = qb * 64;
    const int ql0 = warp * 8;

    for (int i = tid; i < 1024; i += 256) {
        int q = i >> 4, dc = (i & 15) * 4;
        float4 v = *(const float4*)&qkv[((size_t)(b * Ntok + qBase + q)) * (3 * Dm) + h * HD + dc];
        Qs[q * 65 + dc + 0] = v.x; Qs[q * 65 + dc + 1] = v.y;
        Qs[q * 65 + dc + 2] = v.z; Qs[q * 65 + dc + 3] = v.w;
    }

    float accX[8], accY[8], Mx[8], Sum[8];
#pragma unroll
    for (int j = 0; j < 8; ++j) {
        accX[j] = 0.f; accY[j] = 0.f; Mx[j] = -INFINITY; Sum[j] = 0.f;
    }

    const int lastChunk = qb;

    for (int c = 0; c <= lastChunk; ++c) {
        __syncthreads();
        for (int i = tid; i < 1024; i += 256) {
            int m = i >> 4, dc = (i & 15) * 4;
            size_t base = ((size_t)(b * Ntok + c * 64 + m)) * (3 * Dm) + h * HD + dc;
            float4 kv = *(const float4*)&qkv[base + Dm];
            float4 vv = *(const float4*)&qkv[base + 2 * Dm];
            Ks[m * 65 + dc + 0] = kv.x; Ks[m * 65 + dc + 1] = kv.y;
            Ks[m * 65 + dc + 2] = kv.z; Ks[m * 65 + dc + 3] = kv.w;
            Vs[m * 68 + dc + 0] = vv.x; Vs[m * 68 + dc + 1] = vv.y;
            Vs[m * 68 + dc + 2] = vv.z; Vs[m * 68 + dc + 3] = vv.w;
        }
        __syncthreads();

        {
            float s1[8], s2[8];
#pragma unroll
            for (int j = 0; j < 8; ++j) { s1[j] = 0.f; s2[j] = 0.f; }
#pragma unroll
            for (int d = 0; d < 64; ++d) {
                float kd1 = Ks[lane * 65 + d];
                float kd2 = Ks[(lane + 32) * 65 + d];
#pragma unroll
                for (int j = 0; j < 8; ++j) {
                    float qd = Qs[(ql0 + j) * 65 + d];
                    s1[j] = fmaf(qd, kd1, s1[j]);
                    s2[j] = fmaf(qd, kd2, s2[j]);
                }
            }
            const int k1 = c * 64 + lane, k2 = k1 + 32;
#pragma unroll
            for (int j = 0; j < 8; ++j) {
                const int l = qBase + ql0 + j;
                if (l < c * 64) continue;
                float a1 = s1[j] * 0.125f, a2 = s2[j] * 0.125f;
                if (k1 > l) a1 = -INFINITY;
                if (k2 > l) a2 = -INFINITY;
                float cm = fmaxf(a1, a2);
#pragma unroll
                for (int off = 16; off > 0; off >>= 1)
                    cm = fmaxf(cm, __shfl_xor_sync(0xFFFFFFFFu, cm, off));
                float newM = fmaxf(Mx[j], cm);
                float scaleOld = __expf(Mx[j] - newM);
                float p1 = (k1 > l) ? 0.f : __expf(a1 - newM);
                float p2 = (k2 > l) ? 0.f : __expf(a2 - newM);
                float rs = p1 + p2;
#pragma unroll
                for (int off = 16; off > 0; off >>= 1)
                    rs += __shfl_xor_sync(0xFFFFFFFFu, rs, off);
                Sum[j] = Sum[j] * scaleOld + rs;
                Mx[j] = newM;
                accX[j] *= scaleOld; accY[j] *= scaleOld;
                Ps[(ql0 + j) * 65 + lane] = p1;
                Ps[(ql0 + j) * 65 + lane + 32] = p2;
            }
            __syncwarp();
#pragma unroll 4
            for (int m = 0; m < 64; ++m) {
                float2 v = *(const float2*)&Vs[m * 68 + 2 * lane];
#pragma unroll
                for (int j = 0; j < 8; ++j) {
                    float p = Ps[(ql0 + j) * 65 + m];
                    accX[j] = fmaf(p, v.x, accX[j]);
                    accY[j] = fmaf(p, v.y, accY[j]);
                }
            }
            __syncwarp();
        }
    }

#pragma unroll
    for (int j = 0; j < 8; ++j) {
        const int l = qBase + ql0 + j;
        float inv = 1.0f / Sum[j];
        size_t ob = ((size_t)(b * Ntok + l)) * Dm + h * HD + 2 * lane;
        __nv_bfloat16 hx, lx, hy, ly;
        split_bf16(accX[j] * inv, hx, lx);
        split_bf16(accY[j] * inv, hy, ly);
        *(__nv_bfloat162*)(ohi + ob) = __nv_bfloat162(hx, hy);
        *(__nv_bfloat162*)(olo + ob) = __nv_bfloat162(lx, ly);
    }
}

// ---------------- final mean over tokens ----------------
__global__ void mean_kernel(const float* __restrict__ hln, float* __restrict__ enc) {
    int idx = blockIdx.x * blockDim.x + threadIdx.x;
    if (idx >= Bx * Dm) return;
    int b = idx / Dm, d = idx - b * Dm;
    float s = 0.f;
    const float* base = hln + (size_t)b * Ntok * Dm + d;
    for (int n = 0; n < Ntok; ++n) s += base[(size_t)n * Dm];
    enc[idx] = s * (1.0f / Ntok);
}

// ---------------- head ----------------
__global__ void head_kernel(const float* __restrict__ enc,
                            const float* __restrict__ h1w, const float* __restrict__ h1b,
                            const float* __restrict__ h2w, const float* __restrict__ h2b,
                            float* __restrict__ out) {
    __shared__ float es[Dm];
    __shared__ float ys[Dm / 2];
    int b = blockIdx.x, tid = threadIdx.x;
    for (int j = tid; j < Dm; j += blockDim.x) es[j] = enc[(size_t)b * Dm + j];
    __syncthreads();
    int j = tid;
    float s = h1b[j];
    const float* wr = h1w + (size_t)j * Dm;
#pragma unroll 4
    for (int d = 0; d < Dm; ++d) s = fmaf(es[d], wr[d], s);
    ys[j] = fmaxf(s, 0.f);
    __syncthreads();
    if (tid < 2) {
        float s2 = h2b[tid];
        const float* w2 = h2w + (size_t)tid * (Dm / 2);
        for (int q = 0; q < Dm / 2; ++q) s2 = fmaf(ys[q], w2[q], s2);
        out[b * 2 + tid] = s2;
    }
}

// ---------------- launch ----------------
extern "C" void kernel_launch(void* const* d_in, const int* in_sizes, int n_in,
                              void* d_out, int out_size) {
    const float* x     = (const float*)d_in[0];
    const float* pp_w  = (const float*)d_in[1];
    const float* pp_b  = (const float*)d_in[2];
    const float* pe    = (const float*)d_in[3];
    const float* ln1_g = (const float*)d_in[4];
    const float* ln1_b = (const float*)d_in[5];
    const float* qkv_w = (const float*)d_in[6];
    const float* out_w = (const float*)d_in[7];
    const float* ln2_g = (const float*)d_in[8];
    const float* ln2_b = (const float*)d_in[9];
    const float* fc1_w = (const float*)d_in[10];
    const float* fc2_w = (const float*)d_in[11];
    const float* lnf_g = (const float*)d_in[12];
    const float* lnf_b = (const float*)d_in[13];
    const float* h1_w  = (const float*)d_in[14];
    const float* h1_b  = (const float*)d_in[15];
    const float* h2_w  = (const float*)d_in[16];
    const float* h2_b  = (const float*)d_in[17];

    float *z, *h, *qkv, *enc;
    __nv_bfloat16 *hh, *hl, *oh, *ol, *fh, *fl;
    __nv_bfloat16 *wqh, *wql, *woh, *wol, *w1h, *w1l, *w2h, *w2l;
    cudaGetSymbolAddress((void**)&z,   g_z);
    cudaGetSymbolAddress((void**)&h,   g_h);
    cudaGetSymbolAddress((void**)&qkv, g_qkv);
    cudaGetSymbolAddress((void**)&enc, g_enc);
    cudaGetSymbolAddress((void**)&hh,  g_hh);  cudaGetSymbolAddress((void**)&hl, g_hl);
    cudaGetSymbolAddress((void**)&oh,  g_oh);  cudaGetSymbolAddress((void**)&ol, g_ol);
    cudaGetSymbolAddress((void**)&fh,  g_fh);  cudaGetSymbolAddress((void**)&fl, g_fl);
    cudaGetSymbolAddress((void**)&wqh, g_wqkv_h); cudaGetSymbolAddress((void**)&wql, g_wqkv_l);
    cudaGetSymbolAddress((void**)&woh, g_wout_h); cudaGetSymbolAddress((void**)&wol, g_wout_l);
    cudaGetSymbolAddress((void**)&w1h, g_wfc1_h); cudaGetSymbolAddress((void**)&w1l, g_wfc1_l);
    cudaGetSymbolAddress((void**)&w2h, g_wfc2_h); cudaGetSymbolAddress((void**)&w2l, g_wfc2_l);

    cudaFuncSetAttribute(wgemm<0>, cudaFuncAttributeMaxDynamicSharedMemorySize, GEMM_SMEM);
    cudaFuncSetAttribute(wgemm<1>, cudaFuncAttributeMaxDynamicSharedMemorySize, GEMM_SMEM);
    cudaFuncSetAttribute(wgemm<2>, cudaFuncAttributeMaxDynamicSharedMemorySize, GEMM_SMEM);
    cudaFuncSetAttribute(attn_kernel, cudaFuncAttributeMaxDynamicSharedMemorySize, ATT_SMEM);

    split_kernel<<<NQKV / 1024, 256>>>(qkv_w, wqh, wql, NQKV);
    split_kernel<<<NOUT / 1024, 256>>>(out_w, woh, wol, NOUT);
    split_kernel<<<NFC1 / 1024, 256>>>(fc1_w, w1h, w1l, NFC1);
    split_kernel<<<NFC2 / 1024, 256>>>(fc2_w, w2h, w2l, NFC2);

    patch_embed_kernel<<<(Mrows * Dm + 255) / 256, 256>>>(x, pp_w, pp_b, pe, z);

    for (int i = 0; i < NL; ++i) {
        ln_kernel<1><<<Mrows / 8, 256>>>(z, ln1_g + i * Dm, ln1_b + i * Dm, nullptr, hh, hl);
        wgemm<0><<<dim3((3 * Dm) / 128, Mrows / 128), 256, GEMM_SMEM>>>(
            hh, hl, wqh + (size_t)i * 3 * Dm * Dm, wql + (size_t)i * 3 * Dm * Dm,
            nullptr, qkv, nullptr, nullptr, 3 * Dm, Dm);
        attn_kernel<<<dim3(Ntok / 64, Hh, Bx), 256, ATT_SMEM>>>(qkv, oh, ol);
        wgemm<1><<<dim3(Dm / 128, Mrows / 128), 256, GEMM_SMEM>>>(
            oh, ol, woh + (size_t)i * Dm * Dm, wol + (size_t)i * Dm * Dm,
            z, z, nullptr, nullptr, Dm, Dm);
        ln_kernel<1><<<Mrows / 8, 256>>>(z, ln2_g + i * Dm, ln2_b + i * Dm, nullptr, hh, hl);
        wgemm<2><<<dim3(DFF / 128, Mrows / 128), 256, GEMM_SMEM>>>(
            hh, hl, w1h + (size_t)i * DFF * Dm, w1l + (size_t)i * DFF * Dm,
            nullptr, nullptr, fh, fl, DFF, Dm);
        wgemm<1><<<dim3(Dm / 128, Mrows / 128), 256, GEMM_SMEM>>>(
            fh, fl, w2h + (size_t)i * Dm * DFF, w2l + (size_t)i * Dm * DFF,
            z, z, nullptr, nullptr, Dm, DFF);
    }

    ln_kernel<0><<<Mrows / 8, 256>>>(z, lnf_g, lnf_b, h, nullptr, nullptr);
    mean_kernel<<<(Bx * Dm + 255) / 256, 256>>>(h, enc);
    head_kernel<<<Bx, Dm / 2>>>(enc, h1_w, h1_b, h2_w, h2_b, (float*)d_out);
}

// round 12
// speedup vs baseline: 1.0875x; 1.0211x over previous
#include <cuda_runtime.h>
#include <cuda_bf16.h>
#include <cstdint>
#include <math.h>

#define Bx 8
#define Ntok 512
#define Dm 768
#define Hh 12
#define HD 64
#define NL 6
#define DFF 3072
#define Mrows (Bx * Ntok)      // 4096
#define Tlen 8192
#define PATCH 16

// ---------------- scratch (device globals; no allocation) ----------------
__device__ float g_z[Mrows * Dm];
__device__ float g_h[Mrows * Dm];
__device__ float g_qkv[Mrows * 3 * Dm];
__device__ float g_enc[Bx * Dm];

__device__ __nv_bfloat16 g_hh[Mrows * Dm],  g_hl[Mrows * Dm];
__device__ __nv_bfloat16 g_oh[Mrows * Dm],  g_ol[Mrows * Dm];
__device__ __nv_bfloat16 g_fh[Mrows * DFF], g_fl[Mrows * DFF];

#define NQKV (NL * 3 * Dm * Dm)
#define NOUT (NL * Dm * Dm)
#define NFC1 (NL * DFF * Dm)
#define NFC2 (NL * Dm * DFF)
__device__ __nv_bfloat16 g_wqkv_h[NQKV], g_wqkv_l[NQKV];
__device__ __nv_bfloat16 g_wout_h[NOUT], g_wout_l[NOUT];
__device__ __nv_bfloat16 g_wfc1_h[NFC1], g_wfc1_l[NFC1];
__device__ __nv_bfloat16 g_wfc2_h[NFC2], g_wfc2_l[NFC2];

// ---------------- helpers ----------------
__device__ __forceinline__ void split_bf16(float x, __nv_bfloat16& h, __nv_bfloat16& l) {
    h = __float2bfloat16_rn(x);
    l = __float2bfloat16_rn(x - __bfloat162float(h));
}
__device__ __forceinline__ uint32_t sw128(uint32_t o) { return o ^ ((o >> 3) & 0x70); }
__device__ __forceinline__ uint32_t smem_u32(const void* p) {
    return (uint32_t)__cvta_generic_to_shared(p);
}
__device__ __forceinline__ void cp16(uint32_t dst, const void* src) {
    asm volatile("cp.async.cg.shared.global [%0], [%1], 16;" :: "r"(dst), "l"(src));
}
__device__ __forceinline__ void ldmx4(uint32_t* r, uint32_t addr) {
    asm volatile("ldmatrix.sync.aligned.m8n8.x4.shared.b16 {%0,%1,%2,%3}, [%4];"
                 : "=r"(r[0]), "=r"(r[1]), "=r"(r[2]), "=r"(r[3]) : "r"(addr));
}
__device__ __forceinline__ void mma16(float* c, const uint32_t* a, const uint32_t* b) {
    asm volatile("mma.sync.aligned.m16n8k16.row.col.f32.bf16.bf16.f32 "
                 "{%0,%1,%2,%3}, {%4,%5,%6,%7}, {%8,%9}, {%0,%1,%2,%3};"
                 : "+f"(c[0]), "+f"(c[1]), "+f"(c[2]), "+f"(c[3])
                 : "r"(a[0]), "r"(a[1]), "r"(a[2]), "r"(a[3]),
                   "r"(b[0]), "r"(b[1]));
}

// ---------------- weight split (vectorized x4) ----------------
__global__ void split_kernel(const float* __restrict__ src,
                             __nv_bfloat16* __restrict__ hi,
                             __nv_bfloat16* __restrict__ lo, int n) {
    int i = (blockIdx.x * 256 + threadIdx.x) * 4;
    if (i >= n) return;
    float4 v = *(const float4*)(src + i);
    __nv_bfloat16 h0, l0, h1, l1, h2, l2, h3, l3;
    split_bf16(v.x, h0, l0); split_bf16(v.y, h1, l1);
    split_bf16(v.z, h2, l2); split_bf16(v.w, h3, l3);
    ushort4 hv, lv;
    hv.x = *(uint16_t*)&h0; hv.y = *(uint16_t*)&h1; hv.z = *(uint16_t*)&h2; hv.w = *(uint16_t*)&h3;
    lv.x = *(uint16_t*)&l0; lv.y = *(uint16_t*)&l1; lv.z = *(uint16_t*)&l2; lv.w = *(uint16_t*)&l3;
    *(ushort4*)(hi + i) = hv;
    *(ushort4*)(lo + i) = lv;
}

// ---------------- patch embed + positional ----------------
__global__ void patch_embed_kernel(const float* __restrict__ x,
                                   const float* __restrict__ pp_w,
                                   const float* __restrict__ pp_b,
                                   const float* __restrict__ pe,
                                   float* __restrict__ z) {
    int idx = blockIdx.x * blockDim.x + threadIdx.x;
    if (idx >= Mrows * Dm) return;
    int row = idx / Dm;
    int d   = idx - row * Dm;
    int b = row >> 9;
    int n = row & 511;
    const float* xr = x + (size_t)b * Tlen + n * PATCH;
    const float* wr = pp_w + (size_t)d * PATCH;
    float s = pp_b[d];
#pragma unroll
    for (int p = 0; p < PATCH; ++p) s += xr[p] * wr[p];
    z[idx] = s + pe[(size_t)n * Dm + d];
}

// ---------------- LayerNorm: warp per row ----------------
template<int OUT>
__global__ __launch_bounds__(256)
void ln_kernel(const float* __restrict__ X,
               const float* __restrict__ gam,
               const float* __restrict__ bet,
               float* __restrict__ Yf,
               __nv_bfloat16* __restrict__ Yh,
               __nv_bfloat16* __restrict__ Yl) {
    const int warp = threadIdx.x >> 5, lane = threadIdx.x & 31;
    const int row = blockIdx.x * 8 + warp;
    const float4* xr = (const float4*)(X + (size_t)row * Dm);
    float4 v[6];
    float s = 0.f;
#pragma unroll
    for (int k = 0; k < 6; ++k) {
        v[k] = xr[lane + 32 * k];
        s += v[k].x + v[k].y + v[k].z + v[k].w;
    }
#pragma unroll
    for (int off = 16; off > 0; off >>= 1) s += __shfl_xor_sync(0xFFFFFFFFu, s, off);
    const float mean = s * (1.0f / Dm);
    float var = 0.f;
#pragma unroll
    for (int k = 0; k < 6; ++k) {
        float a = v[k].x - mean, b = v[k].y - mean, c = v[k].z - mean, d = v[k].w - mean;
        var += a * a + b * b + c * c + d * d;
    }
#pragma unroll
    for (int off = 16; off > 0; off >>= 1) var += __shfl_xor_sync(0xFFFFFFFFu, var, off);
    const float rstd = rsqrtf(var * (1.0f / Dm) + 1e-5f);

#pragma unroll
    for (int k = 0; k < 6; ++k) {
        int j4 = lane + 32 * k;
        float4 g = ((const float4*)gam)[j4];
        float4 b = ((const float4*)bet)[j4];
        float y0 = (v[k].x - mean) * rstd * g.x + b.x;
        float y1 = (v[k].y - mean) * rstd * g.y + b.y;
        float y2 = (v[k].z - mean) * rstd * g.z + b.z;
        float y3 = (v[k].w - mean) * rstd * g.w + b.w;
        if (OUT == 0) {
            ((float4*)(Yf + (size_t)row * Dm))[j4] = make_float4(y0, y1, y2, y3);
        } else {
            __nv_bfloat16 h0, l0, h1, l1, h2, l2, h3, l3;
            split_bf16(y0, h0, l0); split_bf16(y1, h1, l1);
            split_bf16(y2, h2, l2); split_bf16(y3, h3, l3);
            ushort4 hv, lv;
            hv.x = *(uint16_t*)&h0; hv.y = *(uint16_t*)&h1;
            hv.z = *(uint16_t*)&h2; hv.w = *(uint16_t*)&h3;
            lv.x = *(uint16_t*)&l0; lv.y = *(uint16_t*)&l1;
            lv.z = *(uint16_t*)&l2; lv.w = *(uint16_t*)&l3;
            ((ushort4*)(Yh + (size_t)row * Dm))[j4] = hv;
            ((ushort4*)(Yl + (size_t)row * Dm))[j4] = lv;
        }
    }
}

// ---------------- bf16x3 mma.sync GEMM, KTILE=64, 3 stages (round-8 best) ----------------
#define KTILE 64
#define ST_OP 16384
#define STG (4 * ST_OP)
#define NSTAGE 3
#define GEMM_SMEM (NSTAGE * STG + 1024)

template<int EPI>
__global__ __launch_bounds__(256, 1)
void wgemm(const __nv_bfloat16* __restrict__ Ah, const __nv_bfloat16* __restrict__ Al,
           const __nv_bfloat16* __restrict__ Wh, const __nv_bfloat16* __restrict__ Wl,
           const float* __restrict__ Res, float* __restrict__ Cf,
           __nv_bfloat16* __restrict__ Chi, __nv_bfloat16* __restrict__ Clo,
           int Nn, int K) {
    extern __shared__ char dyn_smem[];
    const int tid = threadIdx.x, lane = tid & 31, wid = tid >> 5;
    const int warpM = wid & 1, warpN = wid >> 1;
    uint32_t raw = smem_u32(dyn_smem);
    uint32_t sb0 = (raw + 1023u) & ~1023u;

    const int mBase = blockIdx.y * 128, nBase = blockIdx.x * 128;
    const int KT = K >> 6;

    uint32_t swl[4];
    const __nv_bfloat16 *pAh[4], *pAl[4], *pWh[4], *pWl[4];
#pragma unroll
    for (int i = 0; i < 4; ++i) {
        int q = tid + i * 256;
        int row = q >> 3, c = q & 7;
        swl[i] = sw128((uint32_t)(row * 128 + c * 16));
        size_t ga = (size_t)(mBase + row) * K + c * 8;
        size_t gw = (size_t)(nBase + row) * K + c * 8;
        pAh[i] = Ah + ga; pAl[i] = Al + ga;
        pWh[i] = Wh + gw; pWl[i] = Wl + gw;
    }

    float acc[4][4][4];
#pragma unroll
    for (int i = 0; i < 4; ++i)
#pragma unroll
        for (int j = 0; j < 4; ++j)
#pragma unroll
            for (int q = 0; q < 4; ++q) acc[i][j][q] = 0.f;

#define LOADSTG(kt)                                                              \
    do {                                                                         \
        const int kofs_ = (kt) * KTILE;                                          \
        const uint32_t sb_ = sb0 + ((kt) % NSTAGE) * STG;                        \
        _Pragma("unroll")                                                        \
        for (int i_ = 0; i_ < 4; ++i_) {                                         \
            cp16(sb_ + swl[i_],              pAh[i_] + kofs_);                   \
            cp16(sb_ + ST_OP + swl[i_],      pAl[i_] + kofs_);                   \
            cp16(sb_ + 2 * ST_OP + swl[i_],  pWh[i_] + kofs_);                   \
            cp16(sb_ + 3 * ST_OP + swl[i_],  pWl[i_] + kofs_);                   \
        }                                                                        \
        asm volatile("cp.async.commit_group;" ::: "memory");                     \
    } while (0)

    LOADSTG(0);
    LOADSTG(1);

    const int arow = warpM * 64 + (lane & 15);
    const int akb  = (lane >> 4) << 4;
    const int bprow = warpN * 32 + ((lane >> 4) & 1) * 8 + (lane & 7);
    const int bpkb  = ((lane >> 3) & 1) << 4;

    for (int kt = 0; kt < KT; ++kt) {
        if (kt + 1 < KT) {
            asm volatile("cp.async.wait_group 1;" ::: "memory");
        } else {
            asm volatile("cp.async.wait_group 0;" ::: "memory");
        }
        __syncthreads();
        if (kt + 2 < KT) LOADSTG(kt + 2);

        const uint32_t A0 = sb0 + (kt % NSTAGE) * STG;
        const uint32_t W0 = A0 + 2 * ST_OP;

#pragma unroll
        for (int kc = 0; kc < 4; ++kc) {
            uint32_t ah[4][4], al[4][4];
#pragma unroll
            for (int i = 0; i < 4; ++i) {
                uint32_t off = sw128((uint32_t)((arow + i * 16) * 128 + kc * 32 + akb));
                ldmx4(ah[i], A0 + off);
                ldmx4(al[i], A0 + ST_OP + off);
            }
            uint32_t bh[4][2], bl[4][2];
#pragma unroll
            for (int jp = 0; jp < 2; ++jp) {
                uint32_t off = sw128((uint32_t)((bprow + jp * 16) * 128 + kc * 32 + bpkb));
                uint32_t r[4];
                ldmx4(r, W0 + off);
                bh[2 * jp][0] = r[0]; bh[2 * jp][1] = r[1];
                bh[2 * jp + 1][0] = r[2]; bh[2 * jp + 1][1] = r[3];
                ldmx4(r, W0 + ST_OP + off);
                bl[2 * jp][0] = r[0]; bl[2 * jp][1] = r[1];
                bl[2 * jp + 1][0] = r[2]; bl[2 * jp + 1][1] = r[3];
            }
#pragma unroll
            for (int i = 0; i < 4; ++i)
#pragma unroll
                for (int j = 0; j < 4; ++j) {
                    mma16(acc[i][j], ah[i], bh[j]);
                    mma16(acc[i][j], ah[i], bl[j]);
                    mma16(acc[i][j], al[i], bh[j]);
                }
        }
    }

    const int erow = warpM * 64 + (lane >> 2);
    const int ecol = warpN * 32 + (lane & 3) * 2;
#pragma unroll
    for (int i = 0; i < 4; ++i) {
        int row0 = mBase + erow + i * 16;
#pragma unroll
        for (int j = 0; j < 4; ++j) {
            int col = nBase + ecol + j * 8;
            size_t g0 = (size_t)row0 * Nn + col;
            size_t g1 = g0 + (size_t)8 * Nn;
            float v0 = acc[i][j][0], v1 = acc[i][j][1];
            float v2 = acc[i][j][2], v3 = acc[i][j][3];
            if (EPI == 0) {
                *(float2*)(Cf + g0) = make_float2(v0, v1);
                *(float2*)(Cf + g1) = make_float2(v2, v3);
            } else if (EPI == 1) {
                float2 r0 = *(const float2*)(Res + g0);
                float2 r1 = *(const float2*)(Res + g1);
                *(float2*)(Cf + g0) = make_float2(v0 + r0.x, v1 + r0.y);
                *(float2*)(Cf + g1) = make_float2(v2 + r1.x, v3 + r1.y);
            } else {
                v0 = 0.5f * v0 * (1.0f + erff(v0 * 0.70710678118654752f));
                v1 = 0.5f * v1 * (1.0f + erff(v1 * 0.70710678118654752f));
                v2 = 0.5f * v2 * (1.0f + erff(v2 * 0.70710678118654752f));
                v3 = 0.5f * v3 * (1.0f + erff(v3 * 0.70710678118654752f));
                __nv_bfloat16 h0, l0, h1, l1, h2, l2, h3, l3;
                split_bf16(v0, h0, l0); split_bf16(v1, h1, l1);
                split_bf16(v2, h2, l2); split_bf16(v3, h3, l3);
                *(__nv_bfloat162*)(Chi + g0) = __nv_bfloat162(h0, h1);
                *(__nv_bfloat162*)(Clo + g0) = __nv_bfloat162(l0, l1);
                *(__nv_bfloat162*)(Chi + g1) = __nv_bfloat162(h2, h3);
                *(__nv_bfloat162*)(Clo + g1) = __nv_bfloat162(l2, l3);
            }
        }
    }
}

// ---------------- causal attention v4: 64 q/CTA, register-prefetched K/V chunks ----------------
#define ATT_KS   0
#define ATT_VS   (64 * 65)
#define ATT_QS   (ATT_VS + 64 * 68)
#define ATT_PS   (ATT_QS + 64 * 65)
#define ATT_SMEM ((ATT_PS + 64 * 65) * (int)sizeof(float))   // 67328 B

__global__ __launch_bounds__(256)
void attn_kernel(const float* __restrict__ qkv,
                 __nv_bfloat16* __restrict__ ohi, __nv_bfloat16* __restrict__ olo) {
    extern __shared__ float asm_[];
    float* Ks = asm_ + ATT_KS;
    float* Vs = asm_ + ATT_VS;
    float* Qs = asm_ + ATT_QS;
    float* Ps = asm_ + ATT_PS;
    const int b = blockIdx.z, h = blockIdx.y;
    const int qb = gridDim.x - 1 - blockIdx.x;     // heaviest (most chunks) first
    const int warp = threadIdx.x >> 5, lane = threadIdx.x & 31;
    const int tid = threadIdx.x;
    const int qBase = qb * 64;
    const int ql0 = warp * 8;

    // per-thread K/V loader coordinates: element i covers (m, dc)
    const int mT = tid >> 4;            // row 0..15 (+16 per i)
    const int dcT = (tid & 15) * 4;     // column

    for (int i = tid; i < 1024; i += 256) {
        int q = i >> 4, dc = (i & 15) * 4;
        float4 v = *(const float4*)&qkv[((size_t)(b * Ntok + qBase + q)) * (3 * Dm) + h * HD + dc];
        Qs[q * 65 + dc + 0] = v.x; Qs[q * 65 + dc + 1] = v.y;
        Qs[q * 65 + dc + 2] = v.z; Qs[q * 65 + dc + 3] = v.w;
    }

    float4 kreg[4], vreg[4];
#define LOADCHUNK(c)                                                                     \
    do {                                                                                 \
        _Pragma("unroll")                                                                \
        for (int i_ = 0; i_ < 4; ++i_) {                                                 \
            int m_ = mT + i_ * 16;                                                       \
            size_t base_ = ((size_t)(b * Ntok + (c) * 64 + m_)) * (3 * Dm) + h * HD + dcT; \
            kreg[i_] = *(const float4*)&qkv[base_ + Dm];                                 \
            vreg[i_] = *(const float4*)&qkv[base_ + 2 * Dm];                             \
        }                                                                                \
    } while (0)

    LOADCHUNK(0);

    float accX[8], accY[8], Mx[8], Sum[8];
#pragma unroll
    for (int j = 0; j < 8; ++j) {
        accX[j] = 0.f; accY[j] = 0.f; Mx[j] = -INFINITY; Sum[j] = 0.f;
    }

    const int lastChunk = qb;

    for (int c = 0; c <= lastChunk; ++c) {
        __syncthreads();   // all warps done reading previous chunk's Ks/Vs
#pragma unroll
        for (int i = 0; i < 4; ++i) {
            int m = mT + i * 16;
            Ks[m * 65 + dcT + 0] = kreg[i].x; Ks[m * 65 + dcT + 1] = kreg[i].y;
            Ks[m * 65 + dcT + 2] = kreg[i].z; Ks[m * 65 + dcT + 3] = kreg[i].w;
            Vs[m * 68 + dcT + 0] = vreg[i].x; Vs[m * 68 + dcT + 1] = vreg[i].y;
            Vs[m * 68 + dcT + 2] = vreg[i].z; Vs[m * 68 + dcT + 3] = vreg[i].w;
        }
        __syncthreads();
        if (c < lastChunk) LOADCHUNK(c + 1);

        {
            float s1[8], s2[8];
#pragma unroll
            for (int j = 0; j < 8; ++j) { s1[j] = 0.f; s2[j] = 0.f; }
#pragma unroll
            for (int d = 0; d < 64; ++d) {
                float kd1 = Ks[lane * 65 + d];
                float kd2 = Ks[(lane + 32) * 65 + d];
#pragma unroll
                for (int j = 0; j < 8; ++j) {
                    float qd = Qs[(ql0 + j) * 65 + d];
                    s1[j] = fmaf(qd, kd1, s1[j]);
                    s2[j] = fmaf(qd, kd2, s2[j]);
                }
            }
            const int k1 = c * 64 + lane, k2 = k1 + 32;
#pragma unroll
            for (int j = 0; j < 8; ++j) {
                const int l = qBase + ql0 + j;
                float a1 = s1[j] * 0.125f, a2 = s2[j] * 0.125f;
                if (k1 > l) a1 = -INFINITY;
                if (k2 > l) a2 = -INFINITY;
                float cm = fmaxf(a1, a2);
#pragma unroll
                for (int off = 16; off > 0; off >>= 1)
                    cm = fmaxf(cm, __shfl_xor_sync(0xFFFFFFFFu, cm, off));
                float newM = fmaxf(Mx[j], cm);
                float scaleOld = __expf(Mx[j] - newM);
                float p1 = (k1 > l) ? 0.f : __expf(a1 - newM);
                float p2 = (k2 > l) ? 0.f : __expf(a2 - newM);
                float rs = p1 + p2;
#pragma unroll
                for (int off = 16; off > 0; off >>= 1)
                    rs += __shfl_xor_sync(0xFFFFFFFFu, rs, off);
                Sum[j] = Sum[j] * scaleOld + rs;
                Mx[j] = newM;
                accX[j] *= scaleOld; accY[j] *= scaleOld;
                Ps[(ql0 + j) * 65 + lane] = p1;
                Ps[(ql0 + j) * 65 + lane + 32] = p2;
            }
            __syncwarp();
#pragma unroll 4
            for (int m = 0; m < 64; ++m) {
                float2 v = *(const float2*)&Vs[m * 68 + 2 * lane];
#pragma unroll
                for (int j = 0; j < 8; ++j) {
                    float p = Ps[(ql0 + j) * 65 + m];
                    accX[j] = fmaf(p, v.x, accX[j]);
                    accY[j] = fmaf(p, v.y, accY[j]);
                }
            }
            __syncwarp();
        }
    }

#pragma unroll
    for (int j = 0; j < 8; ++j) {
        const int l = qBase + ql0 + j;
        float inv = 1.0f / Sum[j];
        size_t ob = ((size_t)(b * Ntok + l)) * Dm + h * HD + 2 * lane;
        __nv_bfloat16 hx, lx, hy, ly;
        split_bf16(accX[j] * inv, hx, lx);
        split_bf16(accY[j] * inv, hy, ly);
        *(__nv_bfloat162*)(ohi + ob) = __nv_bfloat162(hx, hy);
        *(__nv_bfloat162*)(olo + ob) = __nv_bfloat162(lx, ly);
    }
}

// ---------------- final mean over tokens ----------------
__global__ void mean_kernel(const float* __restrict__ hln, float* __restrict__ enc) {
    int idx = blockIdx.x * blockDim.x + threadIdx.x;
    if (idx >= Bx * Dm) return;
    int b = idx / Dm, d = idx - b * Dm;
    float s = 0.f;
    const float* base = hln + (size_t)b * Ntok * Dm + d;
    for (int n = 0; n < Ntok; ++n) s += base[(size_t)n * Dm];
    enc[idx] = s * (1.0f / Ntok);
}

// ---------------- head ----------------
__global__ void head_kernel(const float* __restrict__ enc,
                            const float* __restrict__ h1w, const float* __restrict__ h1b,
                            const float* __restrict__ h2w, const float* __restrict__ h2b,
                            float* __restrict__ out) {
    __shared__ float es[Dm];
    __shared__ float ys[Dm / 2];
    int b = blockIdx.x, tid = threadIdx.x;
    for (int j = tid; j < Dm; j += blockDim.x) es[j] = enc[(size_t)b * Dm + j];
    __syncthreads();
    int j = tid;
    float s = h1b[j];
    const float* wr = h1w + (size_t)j * Dm;
#pragma unroll 4
    for (int d = 0; d < Dm; ++d) s = fmaf(es[d], wr[d], s);
    ys[j] = fmaxf(s, 0.f);
    __syncthreads();
    if (tid < 2) {
        float s2 = h2b[tid];
        const float* w2 = h2w + (size_t)tid * (Dm / 2);
        for (int q = 0; q < Dm / 2; ++q) s2 = fmaf(ys[q], w2[q], s2);
        out[b * 2 + tid] = s2;
    }
}

// ---------------- launch ----------------
extern "C" void kernel_launch(void* const* d_in, const int* in_sizes, int n_in,
                              void* d_out, int out_size) {
    const float* x     = (const float*)d_in[0];
    const float* pp_w  = (const float*)d_in[1];
    const float* pp_b  = (const float*)d_in[2];
    const float* pe    = (const float*)d_in[3];
    const float* ln1_g = (const float*)d_in[4];
    const float* ln1_b = (const float*)d_in[5];
    const float* qkv_w = (const float*)d_in[6];
    const float* out_w = (const float*)d_in[7];
    const float* ln2_g = (const float*)d_in[8];
    const float* ln2_b = (const float*)d_in[9];
    const float* fc1_w = (const float*)d_in[10];
    const float* fc2_w = (const float*)d_in[11];
    const float* lnf_g = (const float*)d_in[12];
    const float* lnf_b = (const float*)d_in[13];
    const float* h1_w  = (const float*)d_in[14];
    const float* h1_b  = (const float*)d_in[15];
    const float* h2_w  = (const float*)d_in[16];
    const float* h2_b  = (const float*)d_in[17];

    float *z, *h, *qkv, *enc;
    __nv_bfloat16 *hh, *hl, *oh, *ol, *fh, *fl;
    __nv_bfloat16 *wqh, *wql, *woh, *wol, *w1h, *w1l, *w2h, *w2l;
    cudaGetSymbolAddress((void**)&z,   g_z);
    cudaGetSymbolAddress((void**)&h,   g_h);
    cudaGetSymbolAddress((void**)&qkv, g_qkv);
    cudaGetSymbolAddress((void**)&enc, g_enc);
    cudaGetSymbolAddress((void**)&hh,  g_hh);  cudaGetSymbolAddress((void**)&hl, g_hl);
    cudaGetSymbolAddress((void**)&oh,  g_oh);  cudaGetSymbolAddress((void**)&ol, g_ol);
    cudaGetSymbolAddress((void**)&fh,  g_fh);  cudaGetSymbolAddress((void**)&fl, g_fl);
    cudaGetSymbolAddress((void**)&wqh, g_wqkv_h); cudaGetSymbolAddress((void**)&wql, g_wqkv_l);
    cudaGetSymbolAddress((void**)&woh, g_wout_h); cudaGetSymbolAddress((void**)&wol, g_wout_l);
    cudaGetSymbolAddress((void**)&w1h, g_wfc1_h); cudaGetSymbolAddress((void**)&w1l, g_wfc1_l);
    cudaGetSymbolAddress((void**)&w2h, g_wfc2_h); cudaGetSymbolAddress((void**)&w2l, g_wfc2_l);

    cudaFuncSetAttribute(wgemm<0>, cudaFuncAttributeMaxDynamicSharedMemorySize, GEMM_SMEM);
    cudaFuncSetAttribute(wgemm<1>, cudaFuncAttributeMaxDynamicSharedMemorySize, GEMM_SMEM);
    cudaFuncSetAttribute(wgemm<2>, cudaFuncAttributeMaxDynamicSharedMemorySize, GEMM_SMEM);
    cudaFuncSetAttribute(attn_kernel, cudaFuncAttributeMaxDynamicSharedMemorySize, ATT_SMEM);

    split_kernel<<<NQKV / 1024, 256>>>(qkv_w, wqh, wql, NQKV);
    split_kernel<<<NOUT / 1024, 256>>>(out_w, woh, wol, NOUT);
    split_kernel<<<NFC1 / 1024, 256>>>(fc1_w, w1h, w1l, NFC1);
    split_kernel<<<NFC2 / 1024, 256>>>(fc2_w, w2h, w2l, NFC2);

    patch_embed_kernel<<<(Mrows * Dm + 255) / 256, 256>>>(x, pp_w, pp_b, pe, z);

    for (int i = 0; i < NL; ++i) {
        ln_kernel<1><<<Mrows / 8, 256>>>(z, ln1_g + i * Dm, ln1_b + i * Dm, nullptr, hh, hl);
        wgemm<0><<<dim3((3 * Dm) / 128, Mrows / 128), 256, GEMM_SMEM>>>(
            hh, hl, wqh + (size_t)i * 3 * Dm * Dm, wql + (size_t)i * 3 * Dm * Dm,
            nullptr, qkv, nullptr, nullptr, 3 * Dm, Dm);
        attn_kernel<<<dim3(Ntok / 64, Hh, Bx), 256, ATT_SMEM>>>(qkv, oh, ol);
        wgemm<1><<<dim3(Dm / 128, Mrows / 128), 256, GEMM_SMEM>>>(
            oh, ol, woh + (size_t)i * Dm * Dm, wol + (size_t)i * Dm * Dm,
            z, z, nullptr, nullptr, Dm, Dm);
        ln_kernel<1><<<Mrows / 8, 256>>>(z, ln2_g + i * Dm, ln2_b + i * Dm, nullptr, hh, hl);
        wgemm<2><<<dim3(DFF / 128, Mrows / 128), 256, GEMM_SMEM>>>(
            hh, hl, w1h + (size_t)i * DFF * Dm, w1l + (size_t)i * DFF * Dm,
            nullptr, nullptr, fh, fl, DFF, Dm);
        wgemm<1><<<dim3(Dm / 128, Mrows / 128), 256, GEMM_SMEM>>>(
            fh, fl, w2h + (size_t)i * Dm * DFF, w2l + (size_t)i * Dm * DFF,
            z, z, nullptr, nullptr, Dm, DFF);
    }

    ln_kernel<0><<<Mrows / 8, 256>>>(z, lnf_g, lnf_b, h, nullptr, nullptr);
    mean_kernel<<<(Bx * Dm + 255) / 256, 256>>>(h, enc);
    head_kernel<<<Bx, Dm / 2>>>(enc, h1_w, h1_b, h2_w, h2_b, (float*)d_out);
}